// round 9
// baseline (speedup 1.0000x reference)
#include <cuda_runtime.h>
#include <cuda_fp16.h>

// ContrastHead: neighbor-contrastive loss.
//   N=200000 points, K=16 neighbors, C=32 features, T=0.1, weight=0.1, eps=1e-8
// Inputs: features f32 [N*C], labels i32 [N], neighbor_idx [N*K] (int32/int64 detect)
// Output: 1 float.
//
// R9: break the per-point serial chain. Grid-stride loop: each warp processes ~21
// points with a 2-stage pipeline (prefetch next point's idx line + center row while
// computing the current point). idx->gather latency paid once per warp, not per point.
// f16 packed rows (64B) with 5-bit label in LSBs of halfwords 0..4 (R8 layout):
// small register state -> no spills at 256-thread blocks.

#define KNB 16
#define CF  32
#define GBLK 1184   // 148 SMs x 8 blocks

__device__ __align__(16) uint4 g_pack16[200000 * 4];   // 12.8 MB: N rows x 64B
__device__ float2 g_part[GBLK];

// f32 -> f16 rows; thread handles 16B chunk c of row p. Chunk 0 gets label bits.
__global__ __launch_bounds__(256) void ch_pack_kernel(
    const float4* __restrict__ feat4, const int* __restrict__ labels, int n4)
{
    const int i = blockIdx.x * blockDim.x + threadIdx.x;
    if (i >= n4) return;
    const int p = i >> 2, c = i & 3;
    const float4 a = feat4[p * 8 + c * 2];
    const float4 b = feat4[p * 8 + c * 2 + 1];
    __half2 h0 = __floats2half2_rn(a.x, a.y);
    __half2 h1 = __floats2half2_rn(a.z, a.w);
    __half2 h2 = __floats2half2_rn(b.x, b.y);
    __half2 h3 = __floats2half2_rn(b.z, b.w);
    uint4 o;
    o.x = *reinterpret_cast<unsigned*>(&h0);
    o.y = *reinterpret_cast<unsigned*>(&h1);
    o.z = *reinterpret_cast<unsigned*>(&h2);
    o.w = *reinterpret_cast<unsigned*>(&h3);
    if (c == 0) {
        const unsigned lab = (unsigned)labels[p];          // < 17, 5 bits
        o.x = (o.x & ~0x00010001u) | (lab & 1u) | ((lab & 2u) << 15);
        o.y = (o.y & ~0x00010001u) | ((lab >> 2) & 1u) | ((lab & 8u) << 13);
        o.z = (o.z & ~0x00000001u) | ((lab >> 4) & 1u);
    }
    g_pack16[i] = o;
}

__device__ __forceinline__ unsigned lab_decode(uint4 v) {
    return (v.x & 1u) | ((v.x >> 15) & 2u) | ((v.y & 1u) << 2) |
           ((v.y >> 13) & 8u) | ((v.z & 1u) << 4);
}

__device__ __forceinline__ float sqd16(uint4 a, uint4 b) {
    float s = 0.0f;
    const unsigned* pa = reinterpret_cast<const unsigned*>(&a);
    const unsigned* pb = reinterpret_cast<const unsigned*>(&b);
#pragma unroll
    for (int k = 0; k < 4; k++) {
        const float2 fa = __half22float2(*reinterpret_cast<const __half2*>(&pa[k]));
        const float2 fb = __half22float2(*reinterpret_cast<const __half2*>(&pb[k]));
        const float d0 = fa.x - fb.x, d1 = fa.y - fb.y;
        s = fmaf(d0, d0, s);
        s = fmaf(d1, d1, s);
    }
    return s;
}

__device__ __forceinline__ int load_idx16(const void* nbr, bool is64, int p, int lane) {
    int v = 0;
    if (lane < KNB) {
        if (is64) v = (int)reinterpret_cast<const long long*>(nbr)[(size_t)p * KNB + lane];
        else      v = reinterpret_cast<const int*>(nbr)[(size_t)p * KNB + lane];
    }
    return v;
}

__global__ __launch_bounds__(256) void ch_main_kernel(
    const void* __restrict__ nbr, int n)
{
    const unsigned FULL = 0xffffffffu;
    const int lane = threadIdx.x & 31;
    const int wid  = threadIdx.x >> 5;
    const int s = lane & 3;      // 16B chunk within 64B row
    const int g = lane >> 2;     // group id 0..7

    // dtype detect: int64 -> odd 32-bit words of first 16 entries all zero.
    int probe = 1;
    if (lane < 16) probe = reinterpret_cast<const int*>(nbr)[2 * lane + 1];
    const bool is64 = ((__ballot_sync(FULL, probe == 0) & 0xFFFFu) == 0xFFFFu);

    const int W = gridDim.x * 8;                 // total warps = point stride
    int p = blockIdx.x * 8 + wid;

    float acc_n = 0.0f, acc_d = 0.0f;

    // pipeline prologue: stage point p
    int   idxc = 0;
    uint4 cfc  = make_uint4(0u, 0u, 0u, 0u);
    if (p < n) {
        idxc = load_idx16(nbr, is64, p, lane);
        cfc  = g_pack16[(size_t)p * 4 + s];
    }

    while (p < n) {
        // ---- prefetch next point's idx line + center row ----
        const int pn = p + W;
        const int pl = (pn < n) ? pn : p;
        const int   idxn = load_idx16(nbr, is64, pl, lane);
        const uint4 cfn  = g_pack16[(size_t)pl * 4 + s];

        // ---- current point: 2 batched gathers (8 rows per LDG, 4-lane groups) ----
        const unsigned labc = lab_decode(cfc);
        const int i0 = __shfl_sync(FULL, idxc,     g);
        const int i1 = __shfl_sync(FULL, idxc, 8 + g);
        const uint4 nf0 = g_pack16[(size_t)i0 * 4 + s];
        const uint4 nf1 = g_pack16[(size_t)i1 * 4 + s];

        float s0 = sqd16(cfc, nf0);
        float s1 = sqd16(cfc, nf1);
        s0 += __shfl_xor_sync(FULL, s0, 2);
        s1 += __shfl_xor_sync(FULL, s1, 2);
        s0 += __shfl_xor_sync(FULL, s0, 1);
        s1 += __shfl_xor_sync(FULL, s1, 1);

        // s==0 lane of each group owns the labels -> posmask in sign bit
        unsigned e0 = __float_as_uint(s0);
        unsigned e1 = __float_as_uint(s1);
        if (s == 0) {
            if (lab_decode(nf0) == labc) e0 |= 0x80000000u;
            if (lab_decode(nf1) == labc) e1 |= 0x80000000u;
        }

        // owner lane j (0..15): neighbor j = (j>>3)*8 + (j&7); source lane (j&7)*4
        const int srcl = (lane & 7) << 2;
        const unsigned w0 = __shfl_sync(FULL, e0, srcl);
        const unsigned w1 = __shfl_sync(FULL, e1, srcl);
        const unsigned w  = (lane >> 3) ? w1 : w0;     // valid for lanes 0..15

        const float dist2 = __uint_as_float(w & 0x7FFFFFFFu);
        const bool ispos  = (lane < KNB) && (w >> 31);

        const float nd = (lane < KNB) ? -sqrtf(dist2 + 1e-8f) : -1e30f;

        float m = nd;
        m = fmaxf(m, __shfl_xor_sync(FULL, m, 8));
        m = fmaxf(m, __shfl_xor_sync(FULL, m, 4));
        m = fmaxf(m, __shfl_xor_sync(FULL, m, 2));
        m = fmaxf(m, __shfl_xor_sync(FULL, m, 1));

        const float e = (lane < KNB) ? __expf((nd - m) * 10.0f) : 0.0f;  // 1/T = 10
        float pos = ispos ? e : 0.0f;
        float neg = e;
#pragma unroll
        for (int off = 8; off >= 1; off >>= 1) {
            pos += __shfl_xor_sync(FULL, pos, off);
            neg += __shfl_xor_sync(FULL, neg, off);
        }
        const int cnt = __popc(__ballot_sync(FULL, ispos) & 0xFFFFu);

        if (lane == 0) {
            const float pm = (cnt > 0 && cnt < KNB) ? 1.0f : 0.0f;
            const float loss = -__logf(pos / neg + 1e-8f);
            acc_n = fmaf(loss, pm, acc_n);
            acc_d += pm;
        }

        p = pn; idxc = idxn; cfc = cfn;
    }

    __shared__ float sn[8], sd[8];
    if (lane == 0) { sn[wid] = acc_n; sd[wid] = acc_d; }
    __syncthreads();
    if (threadIdx.x == 0) {
        float a = 0.0f, b = 0.0f;
#pragma unroll
        for (int i = 0; i < 8; i++) { a += sn[i]; b += sd[i]; }
        g_part[blockIdx.x] = make_float2(a, b);
    }
}

__global__ __launch_bounds__(1024) void ch_finalize_kernel(
    float* __restrict__ out, int nblocks)
{
    const unsigned FULL = 0xffffffffu;
    float a = 0.0f, b = 0.0f;
    for (int i = threadIdx.x; i < nblocks; i += 1024) {
        float2 v = g_part[i];
        a += v.x; b += v.y;
    }
#pragma unroll
    for (int off = 16; off >= 1; off >>= 1) {
        a += __shfl_xor_sync(FULL, a, off);
        b += __shfl_xor_sync(FULL, b, off);
    }
    __shared__ float sa[32], sb[32];
    if ((threadIdx.x & 31) == 0) { sa[threadIdx.x >> 5] = a; sb[threadIdx.x >> 5] = b; }
    __syncthreads();
    if (threadIdx.x == 0) {
        double na = 0.0, nb = 0.0;
#pragma unroll
        for (int i = 0; i < 32; i++) { na += sa[i]; nb += sb[i]; }
        if (nb < 1.0) nb = 1.0;
        out[0] = (float)(na / nb * 0.1);   // WEIGHT = 0.1
    }
}

extern "C" void kernel_launch(void* const* d_in, const int* in_sizes, int n_in,
                              void* d_out, int out_size) {
    const float* feat   = (const float*)d_in[0];
    const int*   labels = (const int*)d_in[1];
    const void*  nbr    = (const void*)d_in[2];
    float* out = (float*)d_out;
    (void)n_in; (void)out_size;

    const int n = in_sizes[1];     // N points
    const int n4 = n * 4;          // 16B output chunks

    ch_pack_kernel<<<(n4 + 255) / 256, 256>>>((const float4*)feat, labels, n4);

    int blocks = (n + 7) / 8;
    if (blocks > GBLK) blocks = GBLK;
    ch_main_kernel<<<blocks, 256>>>(nbr, n);

    ch_finalize_kernel<<<1, 1024>>>(out, blocks);
}

// round 10
// speedup vs baseline: 1.1294x; 1.1294x over previous
#include <cuda_runtime.h>

// ContrastHead: neighbor-contrastive loss.
//   N=200000 points, K=16 neighbors, C=32 features, T=0.1, weight=0.1, eps=1e-8
// Inputs: features f32 [N*C], labels i32 [N], neighbor_idx [N*K] (int32/int64 detect)
// Output: 1 float.
//
// R10: revert to the empirically fastest structure (R1 main: f32 quarter-warp gather,
// direct label gather, warp-per-point) with the two known fixes: in-kernel dtype
// detect (kills the 4.9us init kernel) and per-block partials (kills double atomics).
// No pack prepass. Main is launch 0 -> ncu (-s 5 -c 1) will finally profile it.

#define KNB 16
#define CF  32
#define MAXBLK 25024

__device__ float2 g_part[MAXBLK];

__global__ __launch_bounds__(256) void ch_main_kernel(
    const float* __restrict__ feat,
    const int*   __restrict__ labels,
    const void*  __restrict__ nbr,
    int n)
{
    const unsigned FULL = 0xffffffffu;
    const int lane = threadIdx.x & 31;
    const int wid  = threadIdx.x >> 5;
    const int wp   = (blockIdx.x * blockDim.x + threadIdx.x) >> 5;   // warp -> point
    const bool active = (wp < n);
    const int p = active ? wp : 0;

    // dtype detect: int64 -> odd 32-bit words of first 16 entries all zero.
    int probe = 1;
    if (lane < 16) probe = reinterpret_cast<const int*>(nbr)[2 * lane + 1];
    const bool is64 = ((__ballot_sync(FULL, probe == 0) & 0xFFFFu) == 0xFFFFu);

    // center label (uniform broadcast load)
    const int lab = labels[p];

    // Quarter-warp layout: sublane s in [0,8) holds float4 chunk s of any row.
    const int s = lane & 7;
    const float4 cf = reinterpret_cast<const float4*>(feat + (size_t)p * CF)[s];

    // lanes 0..15: this lane's neighbor index and neighbor label
    int myidx = 0;
    if (lane < KNB) {
        if (is64)
            myidx = (int)reinterpret_cast<const long long*>(nbr)[(size_t)p * KNB + lane];
        else
            myidx = reinterpret_cast<const int*>(nbr)[(size_t)p * KNB + lane];
    }
    const int nblab = labels[(lane < KNB) ? myidx : 0];

    // Distances: iteration t handles neighbors t*4 .. t*4+3, one per 8-lane quarter.
    float dist2 = 0.0f;
#pragma unroll
    for (int t = 0; t < 4; t++) {
        const int j_src = t * 4 + (lane >> 3);
        const int idx = __shfl_sync(FULL, myidx, j_src);
        const float4 nf = reinterpret_cast<const float4*>(feat + (size_t)idx * CF)[s];
        const float d0 = cf.x - nf.x, d1 = cf.y - nf.y;
        const float d2 = cf.z - nf.z, d3 = cf.w - nf.w;
        float sum = d0 * d0;
        sum = fmaf(d1, d1, sum);
        sum = fmaf(d2, d2, sum);
        sum = fmaf(d3, d3, sum);
        sum += __shfl_xor_sync(FULL, sum, 4);
        sum += __shfl_xor_sync(FULL, sum, 2);
        sum += __shfl_xor_sync(FULL, sum, 1);
        // quarter q's total lives at lane q*8; route to owner lane t*4+q
        const float cand = __shfl_sync(FULL, sum, (lane & 3) << 3);
        if ((lane >> 2) == t) dist2 = cand;
    }

    // lanes 0..15 now hold dist^2 for neighbor `lane`
    const float nd = (lane < KNB) ? -sqrtf(dist2 + 1e-8f) : -1e30f;

    // stable softmax: max over the 16 neighbor lanes (xor<16 never crosses halves)
    float m = nd;
    m = fmaxf(m, __shfl_xor_sync(FULL, m, 8));
    m = fmaxf(m, __shfl_xor_sync(FULL, m, 4));
    m = fmaxf(m, __shfl_xor_sync(FULL, m, 2));
    m = fmaxf(m, __shfl_xor_sync(FULL, m, 1));

    const float e = (lane < KNB) ? __expf((nd - m) * 10.0f) : 0.0f;   // 1/T = 10
    const bool ispos = (lane < KNB) && (nblab == lab);
    float pos = ispos ? e : 0.0f;
    float neg = e;
#pragma unroll
    for (int off = 8; off >= 1; off >>= 1) {
        pos += __shfl_xor_sync(FULL, pos, off);
        neg += __shfl_xor_sync(FULL, neg, off);
    }
    const int cnt = __popc(__ballot_sync(FULL, ispos) & 0xFFFFu);

    __shared__ float sn[8], sd[8];
    if (lane == 0) {
        const float pm = (active && cnt > 0 && cnt < KNB) ? 1.0f : 0.0f;
        const float loss = -__logf(pos / neg + 1e-8f);
        sn[wid] = loss * pm;
        sd[wid] = pm;
    }
    __syncthreads();
    if (threadIdx.x == 0) {
        float a = 0.0f, b = 0.0f;
#pragma unroll
        for (int i = 0; i < 8; i++) { a += sn[i]; b += sd[i]; }
        g_part[blockIdx.x] = make_float2(a, b);
    }
}

__global__ __launch_bounds__(1024) void ch_finalize_kernel(
    float* __restrict__ out, int nblocks)
{
    const unsigned FULL = 0xffffffffu;
    float a = 0.0f, b = 0.0f;
    for (int i = threadIdx.x; i < nblocks; i += 1024) {
        float2 v = g_part[i];
        a += v.x; b += v.y;
    }
#pragma unroll
    for (int off = 16; off >= 1; off >>= 1) {
        a += __shfl_xor_sync(FULL, a, off);
        b += __shfl_xor_sync(FULL, b, off);
    }
    __shared__ float sa[32], sb[32];
    if ((threadIdx.x & 31) == 0) { sa[threadIdx.x >> 5] = a; sb[threadIdx.x >> 5] = b; }
    __syncthreads();
    if (threadIdx.x == 0) {
        double na = 0.0, nb = 0.0;
#pragma unroll
        for (int i = 0; i < 32; i++) { na += sa[i]; nb += sb[i]; }
        if (nb < 1.0) nb = 1.0;
        out[0] = (float)(na / nb * 0.1);   // WEIGHT = 0.1
    }
}

extern "C" void kernel_launch(void* const* d_in, const int* in_sizes, int n_in,
                              void* d_out, int out_size) {
    const float* feat   = (const float*)d_in[0];
    const int*   labels = (const int*)d_in[1];
    const void*  nbr    = (const void*)d_in[2];
    float* out = (float*)d_out;
    (void)n_in; (void)out_size;

    const int n = in_sizes[1];        // N points
    const int blocks = (n + 7) / 8;   // warp per point, 8 warps/block

    ch_main_kernel<<<blocks, 256>>>(feat, labels, nbr, n);
    ch_finalize_kernel<<<1, 1024>>>(out, blocks);
}

// round 11
// speedup vs baseline: 1.2358x; 1.0942x over previous
#include <cuda_runtime.h>

// ContrastHead: neighbor-contrastive loss.
//   N=200000 points, K=16 neighbors, C=32 features, T=0.1, weight=0.1, eps=1e-8
// Inputs: features f32 [N*C], labels i32 [N], neighbor_idx [N*K] (int32/int64 detect)
// Output: 1 float.
//
// R11: R10 main (best measured: f32 quarter-warp gather, in-kernel dtype detect)
// + R1 epilogue (per-block double atomics -> 2 globals; they overlap with block
// retirements so they're free) + self-resetting finalize (reads, writes out, zeroes
// the accumulators for the next graph replay). Kills R10's 11us finalize.

#define KNB 16
#define CF  32

__device__ double g_num = 0.0;   // zero at load; finalize re-zeroes after each read
__device__ double g_den = 0.0;

__global__ __launch_bounds__(256) void ch_main_kernel(
    const float* __restrict__ feat,
    const int*   __restrict__ labels,
    const void*  __restrict__ nbr,
    int n)
{
    const unsigned FULL = 0xffffffffu;
    const int lane = threadIdx.x & 31;
    const int wid  = threadIdx.x >> 5;
    const int wp   = (blockIdx.x * blockDim.x + threadIdx.x) >> 5;   // warp -> point
    const bool active = (wp < n);
    const int p = active ? wp : 0;

    // dtype detect: int64 -> odd 32-bit words of first 16 entries all zero.
    int probe = 1;
    if (lane < 16) probe = reinterpret_cast<const int*>(nbr)[2 * lane + 1];
    const bool is64 = ((__ballot_sync(FULL, probe == 0) & 0xFFFFu) == 0xFFFFu);

    // center label (uniform broadcast load)
    const int lab = labels[p];

    // Quarter-warp layout: sublane s in [0,8) holds float4 chunk s of any row.
    const int s = lane & 7;
    const float4 cf = reinterpret_cast<const float4*>(feat + (size_t)p * CF)[s];

    // lanes 0..15: this lane's neighbor index and neighbor label
    int myidx = 0;
    if (lane < KNB) {
        if (is64)
            myidx = (int)reinterpret_cast<const long long*>(nbr)[(size_t)p * KNB + lane];
        else
            myidx = reinterpret_cast<const int*>(nbr)[(size_t)p * KNB + lane];
    }
    const int nblab = labels[(lane < KNB) ? myidx : 0];

    // Distances: iteration t handles neighbors t*4 .. t*4+3, one per 8-lane quarter.
    float dist2 = 0.0f;
#pragma unroll
    for (int t = 0; t < 4; t++) {
        const int j_src = t * 4 + (lane >> 3);
        const int idx = __shfl_sync(FULL, myidx, j_src);
        const float4 nf = reinterpret_cast<const float4*>(feat + (size_t)idx * CF)[s];
        const float d0 = cf.x - nf.x, d1 = cf.y - nf.y;
        const float d2 = cf.z - nf.z, d3 = cf.w - nf.w;
        float sum = d0 * d0;
        sum = fmaf(d1, d1, sum);
        sum = fmaf(d2, d2, sum);
        sum = fmaf(d3, d3, sum);
        sum += __shfl_xor_sync(FULL, sum, 4);
        sum += __shfl_xor_sync(FULL, sum, 2);
        sum += __shfl_xor_sync(FULL, sum, 1);
        // quarter q's total lives at lane q*8; route to owner lane t*4+q
        const float cand = __shfl_sync(FULL, sum, (lane & 3) << 3);
        if ((lane >> 2) == t) dist2 = cand;
    }

    // lanes 0..15 now hold dist^2 for neighbor `lane`
    const float nd = (lane < KNB) ? -sqrtf(dist2 + 1e-8f) : -1e30f;

    // stable softmax: max over the 16 neighbor lanes (xor<16 never crosses halves)
    float m = nd;
    m = fmaxf(m, __shfl_xor_sync(FULL, m, 8));
    m = fmaxf(m, __shfl_xor_sync(FULL, m, 4));
    m = fmaxf(m, __shfl_xor_sync(FULL, m, 2));
    m = fmaxf(m, __shfl_xor_sync(FULL, m, 1));

    const float e = (lane < KNB) ? __expf((nd - m) * 10.0f) : 0.0f;   // 1/T = 10
    const bool ispos = (lane < KNB) && (nblab == lab);
    float pos = ispos ? e : 0.0f;
    float neg = e;
#pragma unroll
    for (int off = 8; off >= 1; off >>= 1) {
        pos += __shfl_xor_sync(FULL, pos, off);
        neg += __shfl_xor_sync(FULL, neg, off);
    }
    const int cnt = __popc(__ballot_sync(FULL, ispos) & 0xFFFFu);

    __shared__ float sn[8], sd[8];
    if (lane == 0) {
        const float pm = (active && cnt > 0 && cnt < KNB) ? 1.0f : 0.0f;
        const float loss = -__logf(pos / neg + 1e-8f);
        sn[wid] = loss * pm;
        sd[wid] = pm;
    }
    __syncthreads();
    if (threadIdx.x == 0) {
        float a = 0.0f, b = 0.0f;
#pragma unroll
        for (int i = 0; i < 8; i++) { a += sn[i]; b += sd[i]; }
        atomicAdd(&g_num, (double)a);
        atomicAdd(&g_den, (double)b);
    }
}

// Reads accumulators, writes the scalar loss, then RESETS them so the next graph
// replay starts from zero (deterministic: identical work and output every call).
__global__ void ch_finalize_kernel(float* __restrict__ out)
{
    if (threadIdx.x == 0) {
        double den = g_den;
        if (den < 1.0) den = 1.0;
        out[0] = (float)(g_num / den * 0.1);   // WEIGHT = 0.1
        g_num = 0.0;
        g_den = 0.0;
    }
}

extern "C" void kernel_launch(void* const* d_in, const int* in_sizes, int n_in,
                              void* d_out, int out_size) {
    const float* feat   = (const float*)d_in[0];
    const int*   labels = (const int*)d_in[1];
    const void*  nbr    = (const void*)d_in[2];
    float* out = (float*)d_out;
    (void)n_in; (void)out_size;

    const int n = in_sizes[1];        // N points
    const int blocks = (n + 7) / 8;   // warp per point, 8 warps/block

    ch_main_kernel<<<blocks, 256>>>(feat, labels, nbr, n);
    ch_finalize_kernel<<<1, 32>>>(out);
}